// round 17
// baseline (speedup 1.0000x reference)
#include <cuda_runtime.h>
#include <cuda_fp16.h>
#include <math.h>
#include <stdint.h>

#define DD   2048
#define K3   6144
#define BB   4
#define TT   2048
#define MTOT 8192   // B*T
#define NCHUNK 4
#define CHUNK (TT / NCHUNK)   // 512

// ---------------- scratch (device globals; no allocation) -------------------
__device__ float g_I [(size_t)MTOT * DD];     // integral  (fp32)
__device__ float g_Dv[(size_t)MTOT * DD];     // derivative(fp32)
__device__ __half g_A[(size_t)MTOT * K3];     // gated features [g0*x|g1*I|g2*D]
__device__ __half g_W[(size_t)DD * K3];       // [Wp|Wi|Wd] concatenated

// ---------------- helpers ----------------------------------------------------
__device__ __forceinline__ uint32_t smem_u32(const void* p) {
    uint32_t a;
    asm("{ .reg .u64 t; cvta.to.shared.u64 t, %1; cvt.u32.u64 %0, t; }"
        : "=r"(a) : "l"(p));
    return a;
}
__device__ __forceinline__ void cp16(uint32_t dst, const void* src) {
    asm volatile("cp.async.cg.shared.global [%0], [%1], 16;\n"
                 :: "r"(dst), "l"(src));
}
#define CP_COMMIT()  asm volatile("cp.async.commit_group;\n" ::: "memory")
#define CP_WAIT(n)   asm volatile("cp.async.wait_group %0;\n" :: "n"(n) : "memory")

__device__ __forceinline__ void ldm_x4(uint32_t* r, uint32_t addr) {
    asm volatile("ldmatrix.sync.aligned.m8n8.x4.shared.b16 {%0,%1,%2,%3}, [%4];"
                 : "=r"(r[0]), "=r"(r[1]), "=r"(r[2]), "=r"(r[3]) : "r"(addr));
}
__device__ __forceinline__ void mma_f16(float* c, const uint32_t* a,
                                        uint32_t b0, uint32_t b1) {
    asm volatile(
        "mma.sync.aligned.m16n8k16.row.col.f32.f16.f16.f32 "
        "{%0,%1,%2,%3}, {%4,%5,%6,%7}, {%8,%9}, {%0,%1,%2,%3};"
        : "+f"(c[0]), "+f"(c[1]), "+f"(c[2]), "+f"(c[3])
        : "r"(a[0]), "r"(a[1]), "r"(a[2]), "r"(a[3]), "r"(b0), "r"(b1));
}

// ---------------------------------------------------------------------------
// Kernel 1a: chunked temporal scan (local pass).
// ---------------------------------------------------------------------------
__global__ void scan_local_kernel(const float* __restrict__ x,
                                  const float* __restrict__ alpha_logit,
                                  const float* __restrict__ beta_logit) {
    int idx = blockIdx.x * blockDim.x + threadIdx.x;
    if (idx >= BB * DD * NCHUNK) return;
    int d  = idx & (DD - 1);
    int bc = idx >> 11;
    int b  = bc & (BB - 1);
    int c  = bc >> 2;

    float a  = 1.0f / (1.0f + expf(-alpha_logit[d]));
    float be = 1.0f / (1.0f + expf(-beta_logit[d]));
    float one_a  = 1.0f - a;
    float one_be = 1.0f - be;

    size_t base = ((size_t)b * TT + (size_t)c * CHUNK) * DD + d;
    const float* xp = x + base;
    float* Ip = g_I  + base;
    float* Dp = g_Dv + base;

    float xprev = (c == 0) ? 0.0f : x[base - DD];
    float s = 0.0f, dv = 0.0f;
    #pragma unroll 8
    for (int t = 0; t < CHUNK; ++t) {
        float xt = xp[(size_t)t * DD];
        s  = a  * s  + one_a  * xt;
        dv = be * dv + one_be * (xt - xprev);
        xprev = xt;
        Ip[(size_t)t * DD] = s;
        Dp[(size_t)t * DD] = dv;
    }
}

// ---------------------------------------------------------------------------
// Kernel 1b: scan fixup (linear recurrences; truncated geometric correction).
// ---------------------------------------------------------------------------
__global__ void scan_fix_kernel(const float* __restrict__ alpha_logit,
                                const float* __restrict__ beta_logit) {
    int idx = blockIdx.x * blockDim.x + threadIdx.x;
    if (idx >= BB * DD) return;
    int d = idx & (DD - 1);
    int b = idx >> 11;

    float a  = 1.0f / (1.0f + expf(-alpha_logit[d]));
    float be = 1.0f / (1.0f + expf(-beta_logit[d]));

    float* Ip = g_I  + (size_t)b * TT * DD + d;
    float* Dp = g_Dv + (size_t)b * TT * DD + d;

    float S  = Ip[(size_t)(CHUNK - 1) * DD];
    float Dv = Dp[(size_t)(CHUNK - 1) * DD];

    for (int c = 1; c < NCHUNK; ++c) {
        float* Ic = Ip + (size_t)c * CHUNK * DD;
        float* Dc = Dp + (size_t)c * CHUNK * DD;
        float fa = a;
        for (int j = 0; j < CHUNK && fa > 1e-10f; ++j) {
            Ic[(size_t)j * DD] += fa * S;
            fa *= a;
        }
        float fb = be;
        for (int j = 0; j < CHUNK && fb > 1e-10f; ++j) {
            Dc[(size_t)j * DD] += fb * Dv;
            fb *= be;
        }
        S  = Ic[(size_t)(CHUNK - 1) * DD];
        Dv = Dc[(size_t)(CHUNK - 1) * DD];
    }
}

// ---------------------------------------------------------------------------
// Kernel 2: W -> concatenated fp16: W'[o, 0:2048|2048:4096|4096:6144]
// ---------------------------------------------------------------------------
__global__ void wconv_kernel(const float* __restrict__ Wp,
                             const float* __restrict__ Wi,
                             const float* __restrict__ Wd) {
    size_t i4 = (size_t)blockIdx.x * blockDim.x + threadIdx.x;
    if (i4 >= (size_t)DD * K3 / 4) return;
    size_t idx = i4 * 4;
    int o = (int)(idx / K3);
    int k = (int)(idx % K3);
    const float* src = (k < DD)     ? Wp + (size_t)o * DD + k
                     : (k < 2 * DD) ? Wi + (size_t)o * DD + (k - DD)
                                    : Wd + (size_t)o * DD + (k - 2 * DD);
    float4 v = *(const float4*)src;
    __half2* hp = (__half2*)(g_W + idx);
    hp[0] = __floats2half2_rn(v.x, v.y);
    hp[1] = __floats2half2_rn(v.z, v.w);
}

// ---------------------------------------------------------------------------
// Kernel 3: gates + fp16 emit, register-fused (one global read of x/I/D).
// ---------------------------------------------------------------------------
__global__ __launch_bounds__(256)
void gate_kernel(const float* __restrict__ x,
                 const float* __restrict__ Wg,
                 const float* __restrict__ Wgb) {
    int m    = blockIdx.x;
    int tid  = threadIdx.x;
    int lane = tid & 31;
    int wrp  = tid >> 5;

    const float4* xr = (const float4*)(x    + (size_t)m * DD);
    const float4* Ir = (const float4*)(g_I  + (size_t)m * DD);
    const float4* Dr = (const float4*)(g_Dv + (size_t)m * DD);
    const float4* W0 = (const float4*)Wg;
    const float4* W1 = (const float4*)(Wg + K3);
    const float4* W2 = (const float4*)(Wg + 2 * K3);

    float4 xv[2], iv[2], dv[2];
    float a0 = 0.f, a1 = 0.f, a2 = 0.f;
    #pragma unroll
    for (int it = 0; it < 2; ++it) {
        int q = tid + it * 256;
        xv[it] = xr[q]; iv[it] = Ir[q]; dv[it] = Dr[q];
        float4 wa, wb, wc;
        wa = W0[q]; wb = W0[q + 512]; wc = W0[q + 1024];
        a0 += xv[it].x*wa.x + xv[it].y*wa.y + xv[it].z*wa.z + xv[it].w*wa.w
            + iv[it].x*wb.x + iv[it].y*wb.y + iv[it].z*wb.z + iv[it].w*wb.w
            + dv[it].x*wc.x + dv[it].y*wc.y + dv[it].z*wc.z + dv[it].w*wc.w;
        wa = W1[q]; wb = W1[q + 512]; wc = W1[q + 1024];
        a1 += xv[it].x*wa.x + xv[it].y*wa.y + xv[it].z*wa.z + xv[it].w*wa.w
            + iv[it].x*wb.x + iv[it].y*wb.y + iv[it].z*wb.z + iv[it].w*wb.w
            + dv[it].x*wc.x + dv[it].y*wc.y + dv[it].z*wc.z + dv[it].w*wc.w;
        wa = W2[q]; wb = W2[q + 512]; wc = W2[q + 1024];
        a2 += xv[it].x*wa.x + xv[it].y*wa.y + xv[it].z*wa.z + xv[it].w*wa.w
            + iv[it].x*wb.x + iv[it].y*wb.y + iv[it].z*wb.z + iv[it].w*wb.w
            + dv[it].x*wc.x + dv[it].y*wc.y + dv[it].z*wc.z + dv[it].w*wc.w;
    }

    #pragma unroll
    for (int off = 16; off; off >>= 1) {
        a0 += __shfl_xor_sync(0xFFFFFFFFu, a0, off);
        a1 += __shfl_xor_sync(0xFFFFFFFFu, a1, off);
        a2 += __shfl_xor_sync(0xFFFFFFFFu, a2, off);
    }
    __shared__ float red[8][3];
    __shared__ float gsm[3];
    if (lane == 0) { red[wrp][0] = a0; red[wrp][1] = a1; red[wrp][2] = a2; }
    __syncthreads();
    if (tid == 0) {
        float l0 = Wgb[0], l1 = Wgb[1], l2 = Wgb[2];
        #pragma unroll
        for (int w = 0; w < 8; ++w) { l0 += red[w][0]; l1 += red[w][1]; l2 += red[w][2]; }
        float mx = fmaxf(l0, fmaxf(l1, l2));
        float e0 = expf(l0 - mx), e1 = expf(l1 - mx), e2 = expf(l2 - mx);
        float inv = 1.0f / (e0 + e1 + e2);
        gsm[0] = e0 * inv; gsm[1] = e1 * inv; gsm[2] = e2 * inv;
    }
    __syncthreads();
    float g0 = gsm[0], g1 = gsm[1], g2 = gsm[2];

    __half* Ah = g_A + (size_t)m * K3;
    #pragma unroll
    for (int it = 0; it < 2; ++it) {
        int e = (tid + it * 256) * 4;
        uint2 o;
        __half2 h0 = __floats2half2_rn(g0 * xv[it].x, g0 * xv[it].y);
        __half2 h1 = __floats2half2_rn(g0 * xv[it].z, g0 * xv[it].w);
        o.x = *(uint32_t*)&h0; o.y = *(uint32_t*)&h1;
        *(uint2*)(Ah + e) = o;
        h0 = __floats2half2_rn(g1 * iv[it].x, g1 * iv[it].y);
        h1 = __floats2half2_rn(g1 * iv[it].z, g1 * iv[it].w);
        o.x = *(uint32_t*)&h0; o.y = *(uint32_t*)&h1;
        *(uint2*)(Ah + DD + e) = o;
        h0 = __floats2half2_rn(g2 * dv[it].x, g2 * dv[it].y);
        h1 = __floats2half2_rn(g2 * dv[it].z, g2 * dv[it].w);
        o.x = *(uint32_t*)&h0; o.y = *(uint32_t*)&h1;
        *(uint2*)(Ah + 2 * DD + e) = o;
    }
}

// ---------------------------------------------------------------------------
// Kernel 4: mma.sync fp16 GEMM:  y = A * W^T + bias
// Block 128x128, BK=64, 8 warps (4m x 2n), warp 32x64, 2 CTAs/SM.
// 3-stage cp.async pipeline with CROSS-KSTEP ROLLING FRAGMENTS:
//   CP_WAIT(0) at iteration end makes stages i+1 AND i+2 valid after the
//   barrier, so subtick-3 of kstep i prefetches kstep i+1's subtick-0 frags
//   into registers — mma issues immediately after every barrier, and ldsm
//   overlaps mma continuously. cp.async burst placed after kk=0 prefetch so
//   it overlaps the mma phase instead of the ldsm phase.
// ---------------------------------------------------------------------------
#define NKSTEP 96               // K3 / 64
#define ROWSTRIDE 144
#define A_OFF 0
#define B_OFF (128 * ROWSTRIDE)            // 18432
#define STAGE_BYTES (2 * 128 * ROWSTRIDE)  // 36864
#define NSTAGE 3
#define GEMM_SMEM (NSTAGE * STAGE_BYTES)   // 110592

__device__ __forceinline__ void issue_stage(uint32_t sbase, int kstep, int slot,
                                            int m0, int n0, int tid) {
    const int k0 = kstep * 64;
    uint32_t sS = sbase + slot * STAGE_BYTES;

    // A tile: 128 rows x 8 chunks of 16B (128B/row) -> 1024 ops, 4/thread
    #pragma unroll
    for (int q = 0; q < 4; ++q) {
        int idx = tid + q * 256;
        int row = idx >> 3, c = idx & 7;
        size_t go = (((size_t)(m0 + row) * K3 + k0) << 1) + c * 16;
        cp16(sS + A_OFF + row * ROWSTRIDE + c * 16, (const char*)g_A + go);
    }
    // B tile: same shape
    #pragma unroll
    for (int q = 0; q < 4; ++q) {
        int idx = tid + q * 256;
        int row = idx >> 3, c = idx & 7;
        size_t go = (((size_t)(n0 + row) * K3 + k0) << 1) + c * 16;
        cp16(sS + B_OFF + row * ROWSTRIDE + c * 16, (const char*)g_W + go);
    }
    CP_COMMIT();
}

__global__ __launch_bounds__(256, 2)
void gemm_kernel(const float* __restrict__ bias, float* __restrict__ y) {
    extern __shared__ char smem[];
    uint32_t sbase = smem_u32(smem);
    const int tid  = threadIdx.x;
    const int wid  = tid >> 5;
    const int lane = tid & 31;
    const int n0 = blockIdx.x * 128;
    const int m0 = blockIdx.y * 128;

    const int m_base = (wid & 3) * 32;    // 4 warps along m
    const int n_base = (wid >> 2) * 64;   // 2 warps along n

    // ldmatrix pattern: row = base + (lane&15), 16B chunk = lane>>4
    const uint32_t frag_off = (lane & 15) * ROWSTRIDE + (lane >> 4) * 16;
    const uint32_t aoff = A_OFF + m_base * ROWSTRIDE + frag_off;
    const uint32_t boff = B_OFF + n_base * ROWSTRIDE + frag_off;

    float acc[2][8][4];
    #pragma unroll
    for (int i = 0; i < 2; ++i)
        #pragma unroll
        for (int j = 0; j < 8; ++j)
            #pragma unroll
            for (int q = 0; q < 4; ++q) acc[i][j][q] = 0.0f;

    // prologue: stages 0 and 1 fully landed before the loop
    issue_stage(sbase, 0, 0, m0, n0, tid);
    issue_stage(sbase, 1, 1, m0, n0, tid);
    CP_WAIT(0);
    __syncthreads();

    // rolling fragments: load subtick-0 of stage 0
    uint32_t a[2][2][4], b[2][4][4];
    {
        uint32_t aA = sbase + aoff;
        uint32_t aB = sbase + boff;
        #pragma unroll
        for (int mt = 0; mt < 2; ++mt) ldm_x4(a[0][mt], aA + mt * (16 * ROWSTRIDE));
        #pragma unroll
        for (int nt = 0; nt < 4; ++nt) ldm_x4(b[0][nt], aB + nt * (16 * ROWSTRIDE));
    }

    int slot = 0;
    for (int i = 0; i < NKSTEP; ++i) {
        int slot_n = (slot + 1 == NSTAGE) ? 0 : slot + 1;          // stage i+1
        int slot_p = (slot + 2 >= NSTAGE) ? slot - 1 : slot + 2;   // stage i+2
        uint32_t aA  = sbase + slot   * STAGE_BYTES + aoff;
        uint32_t aB  = sbase + slot   * STAGE_BYTES + boff;
        uint32_t aAn = sbase + slot_n * STAGE_BYTES + aoff;
        uint32_t aBn = sbase + slot_n * STAGE_BYTES + boff;

        #pragma unroll
        for (int kk = 0; kk < 4; ++kk) {
            int cur = kk & 1, nxt = cur ^ 1;
            // prefetch next subtick (or next kstep's subtick 0: stage i+1 is
            // valid — CP_WAIT(0)+bar at the end of iteration i-1 committed it)
            if (kk < 3) {
                #pragma unroll
                for (int mt = 0; mt < 2; ++mt)
                    ldm_x4(a[nxt][mt], aA + mt * (16 * ROWSTRIDE) + (kk + 1) * 32);
                #pragma unroll
                for (int nt = 0; nt < 4; ++nt)
                    ldm_x4(b[nxt][nt], aB + nt * (16 * ROWSTRIDE) + (kk + 1) * 32);
            } else if (i + 1 < NKSTEP) {
                #pragma unroll
                for (int mt = 0; mt < 2; ++mt)
                    ldm_x4(a[nxt][mt], aAn + mt * (16 * ROWSTRIDE));
                #pragma unroll
                for (int nt = 0; nt < 4; ++nt)
                    ldm_x4(b[nxt][nt], aBn + nt * (16 * ROWSTRIDE));
            }
            // cp.async burst after the first prefetch: overlaps the mma phase
            if (kk == 0 && i + 2 < NKSTEP)
                issue_stage(sbase, i + 2, slot_p, m0, n0, tid);

            // non-trans ldmatrix on n-major B: {r0,r2} = n0-7, {r1,r3} = n8-15
            #pragma unroll
            for (int mt = 0; mt < 2; ++mt)
                #pragma unroll
                for (int nt = 0; nt < 4; ++nt) {
                    mma_f16(acc[mt][2 * nt + 0], a[cur][mt], b[cur][nt][0], b[cur][nt][2]);
                    mma_f16(acc[mt][2 * nt + 1], a[cur][mt], b[cur][nt][1], b[cur][nt][3]);
                }
        }

        // stage i+2 was issued ~a full kstep ago -> this wait is nearly free,
        // and after the barrier BOTH stage i+1 and i+2 are valid for everyone.
        CP_WAIT(0);
        __syncthreads();
        slot = slot_n;
    }

    // epilogue: c frag mapping -> y + bias
    const int g  = lane >> 2;
    const int tg = lane & 3;
    #pragma unroll
    for (int mt = 0; mt < 2; ++mt) {
        int m = m0 + m_base + mt * 16 + g;
        #pragma unroll
        for (int nt = 0; nt < 8; ++nt) {
            int n = n0 + n_base + nt * 8 + tg * 2;
            float b0 = bias[n], b1 = bias[n + 1];
            float2 v0 = make_float2(acc[mt][nt][0] + b0, acc[mt][nt][1] + b1);
            float2 v1 = make_float2(acc[mt][nt][2] + b0, acc[mt][nt][3] + b1);
            *(float2*)(y + (size_t)m * DD + n)       = v0;
            *(float2*)(y + (size_t)(m + 8) * DD + n) = v1;
        }
    }
}

// ---------------------------------------------------------------------------
// Launch
// ---------------------------------------------------------------------------
extern "C" void kernel_launch(void* const* d_in, const int* in_sizes, int n_in,
                              void* d_out, int out_size) {
    const float* x     = (const float*)d_in[0];
    const float* W_p   = (const float*)d_in[1];
    const float* W_i   = (const float*)d_in[2];
    const float* W_d   = (const float*)d_in[3];
    const float* a_log = (const float*)d_in[4];
    const float* b_log = (const float*)d_in[5];
    const float* W_gw  = (const float*)d_in[6];
    const float* W_gb  = (const float*)d_in[7];
    const float* bias  = (const float*)d_in[8];
    float* y = (float*)d_out;

    cudaFuncSetAttribute(gemm_kernel,
                         cudaFuncAttributeMaxDynamicSharedMemorySize, GEMM_SMEM);

    // 1) weight conversion
    {
        int n4 = DD * K3 / 4;
        wconv_kernel<<<(n4 + 255) / 256, 256>>>(W_p, W_i, W_d);
    }
    // 2) chunked temporal scan + carry fixup
    scan_local_kernel<<<(BB * DD * NCHUNK + 127) / 128, 128>>>(x, a_log, b_log);
    scan_fix_kernel<<<(BB * DD + 127) / 128, 128>>>(a_log, b_log);
    // 3) gates + fp16 feature emit
    gate_kernel<<<MTOT, 256>>>(x, W_gw, W_gb);
    // 4) tensor-core GEMM + bias, 2 CTAs/SM
    dim3 grid(DD / 128, MTOT / 128);   // (16, 64) = 1024 blocks
    gemm_kernel<<<grid, 256, GEMM_SMEM>>>(bias, y);
}